// round 16
// baseline (speedup 1.0000x reference)
#include <cuda_runtime.h>
#include <cuda_fp16.h>
#include <cstdint>

#define NN      50000
#define EE      800000
#define INDIM   256
#define HIDC    32
#define NHEADS  8
#define OUTDIM  64
#define C1      (NHEADS * HIDC)   // 256
#define NB      512
#define NB2     64
#define NEGSLOPE 0.2f

typedef unsigned long long u64;

// ---------------- scratch (device globals) ---------------------------------
__device__ int   g_deg   [NN];
__device__ int   g_rowptr[NN];
__device__ int   g_cursor[NN];
__device__ int   g_csrc  [EE];
__device__ int   g_bsums [256];
// fp16 operands
__device__ __align__(16) __half g_Ah  [(size_t)NN * INDIM];
__device__ __align__(16) __half g_Bh  [(size_t)NB * INDIM];
__device__ __align__(16) __half g_Bl  [(size_t)NB * INDIM];
__device__ __align__(16) __half g_xl1h[(size_t)NN * C1];
__device__ __align__(16) __half g_xr1h[(size_t)NN * C1];
__device__ __align__(16) __half g_H1  [(size_t)NN * C1];
__device__ __align__(16) __half g_B2h [(size_t)NB2 * C1];
__device__ __align__(16) __half g_B2l [(size_t)NB2 * C1];
__device__ __align__(16) __half g_xl2h[(size_t)NN * HIDC];
__device__ __align__(16) __half g_xr2h[(size_t)NN * HIDC];

// ---------------- helpers ---------------------------------------------------
__device__ __forceinline__ float lrelu(float v) { return v > 0.f ? v : NEGSLOPE * v; }
__device__ __forceinline__ float elu(float v)   { return v > 0.f ? v : expm1f(v); }

__device__ __forceinline__ uint32_t smem_u32(const void* p)
{
    uint32_t a;
    asm("{ .reg .u64 t; cvta.to.shared.u64 t, %1; cvt.u32.u64 %0, t; }"
        : "=r"(a) : "l"(p));
    return a;
}

// fp16 tensor-core mma (sm_80+ base)
#define MMA_F16(d, a0, a1, a2, a3, b0, b1)                                   \
    asm volatile(                                                            \
        "mma.sync.aligned.m16n8k16.row.col.f32.f16.f16.f32 "                 \
        "{%0,%1,%2,%3}, {%4,%5,%6,%7}, {%8,%9}, {%0,%1,%2,%3};"              \
        : "+f"((d)[0]), "+f"((d)[1]), "+f"((d)[2]), "+f"((d)[3])             \
        : "r"(a0), "r"(a1), "r"(a2), "r"(a3), "r"(b0), "r"(b1))

// ldmatrix (sm_75+ base)
#define LDSM_X4(r0, r1, r2, r3, addr)                                        \
    asm volatile("ldmatrix.sync.aligned.m8n8.x4.shared.b16 {%0,%1,%2,%3}, [%4];" \
                 : "=r"(r0), "=r"(r1), "=r"(r2), "=r"(r3) : "r"(addr))

// cp.async (sm_80+ base)
#define CP16(dst_u32, src_ptr) \
    asm volatile("cp.async.cg.shared.global [%0], [%1], 16;" \
                 :: "r"(dst_u32), "l"(src_ptr))
#define CP_COMMIT() asm volatile("cp.async.commit_group;" ::: "memory")
#define CP_WAIT(n)  asm volatile("cp.async.wait_group %0;" :: "n"(n) : "memory")

// ---------------- conversion kernels -----------------------------------------
// merged: x -> Ah and [W1l|W1r] -> Bh/Bl in one launch
__global__ void conv_xw_k(const float* __restrict__ x, __half* __restrict__ Ah,
                          const float* __restrict__ W1l, const float* __restrict__ W1r,
                          __half* __restrict__ Bh, __half* __restrict__ Bl)
{
    size_t i = (size_t)blockIdx.x * blockDim.x + threadIdx.x;
    const size_t NX = (size_t)NN * INDIM;
    if (i < NX) {
        Ah[i] = __float2half(x[i]);
    } else if (i < NX + (size_t)NB * INDIM) {
        size_t j = i - NX;
        int n = (int)(j >> 8);
        int k = (int)(j & 255);
        float v = (n < C1) ? W1l[(size_t)k * C1 + n] : W1r[(size_t)k * C1 + (n - C1)];
        __half h = __float2half(v);
        Bh[j] = h;
        Bl[j] = __float2half(v - __half2float(h));
    }
}

__global__ void conv_w2_k(const float* __restrict__ W2l, const float* __restrict__ W2r,
                          __half* __restrict__ B2h, __half* __restrict__ B2l)
{
    int i = blockIdx.x * blockDim.x + threadIdx.x;
    if (i >= NB2 * C1) return;
    int n = i >> 8;
    int k = i & 255;
    float v = (n < HIDC) ? W2l[(size_t)k * HIDC + n]
                         : W2r[(size_t)k * HIDC + (n - HIDC)];
    __half h = __float2half(v);
    B2h[i] = h;
    B2l[i] = __float2half(v - __half2float(h));
}

// ============================================================================
// GEMM1 via mma.sync fp16 2-product split; outputs fp16 (+bias).
// ============================================================================
#define KCH    32
#define PAD2   40
#define T_ELEM (128 * PAD2)
#define T_BYTE (T_ELEM * 2)          // 10240
#define STG_BYTE (3 * T_BYTE)        // 30720
#define SMEM_BYTES (2 * STG_BYTE)    // 61440

__global__ __launch_bounds__(256)
void gemm1_mma(const __half* __restrict__ Ah,
               const __half* __restrict__ Bh, const __half* __restrict__ Bl,
               const float* __restrict__ bl1, const float* __restrict__ br1,
               __half* __restrict__ Xl, __half* __restrict__ Xr)
{
    extern __shared__ __half sm[];
    const uint32_t smb = smem_u32(sm);

    const int tid  = threadIdx.x;
    const int wid  = tid >> 5;
    const int lane = tid & 31;
    const int wm   = wid & 1;
    const int wn   = wid >> 1;
    const int rowBase = blockIdx.y * 128;
    const int colBase = blockIdx.x * 128;

    const int lr = lane >> 2;
    const int lc = (lane & 3) * 2;

    const int aRowOff = lane & 15;
    const int aKOff   = (lane >> 4) * 8;
    const int bGrp    = lane >> 3;
    const int bRowOff = (lane & 7) + (bGrp >> 1) * 8;
    const int bKOff   = (bGrp & 1) * 8;

#define LOAD_STAGE(stg, kOff) do {                                            \
    uint32_t sb = smb + (stg) * STG_BYTE;                                     \
    for (int idx = tid; idx < 512; idx += 256) {                              \
        int r  = idx >> 2;                                                    \
        int k8 = (idx & 3) * 8;                                               \
        uint32_t soff = (uint32_t)(r * (PAD2 * 2) + k8 * 2);                  \
        int ga = min(rowBase + r, NN - 1);                                    \
        int gb = colBase + r;                                                 \
        CP16(sb + soff,              Ah + (size_t)ga * INDIM + (kOff) + k8);  \
        CP16(sb + T_BYTE + soff,     Bh + (size_t)gb * INDIM + (kOff) + k8);  \
        CP16(sb + 2 * T_BYTE + soff, Bl + (size_t)gb * INDIM + (kOff) + k8);  \
    }                                                                         \
} while (0)

    float acc[4][4][4];
#pragma unroll
    for (int i = 0; i < 4; i++)
#pragma unroll
        for (int j = 0; j < 4; j++)
#pragma unroll
            for (int f = 0; f < 4; f++) acc[i][j][f] = 0.f;

    LOAD_STAGE(0, 0);
    CP_COMMIT();

    for (int kc = 0; kc < 8; kc++) {
        const int stg = kc & 1;
        if (kc + 1 < 8) {
            LOAD_STAGE((kc + 1) & 1, (kc + 1) * KCH);
            CP_COMMIT();
            CP_WAIT(1);
        } else {
            CP_WAIT(0);
        }
        __syncthreads();

        const uint32_t sA_u  = smb + stg * STG_BYTE;
        const uint32_t sBh_u = sA_u + T_BYTE;
        const uint32_t sBl_u = sA_u + 2 * T_BYTE;

#pragma unroll
        for (int ks = 0; ks < 2; ks++) {
            const int k0 = ks * 16;
            uint32_t bh[4][2], bl_[4][2];
#pragma unroll
            for (int jp = 0; jp < 4; jp += 2) {
                uint32_t baddr = (uint32_t)(((wn * 32 + jp * 8 + bRowOff) * PAD2
                                            + k0 + bKOff) * 2);
                LDSM_X4(bh[jp][0], bh[jp][1], bh[jp + 1][0], bh[jp + 1][1],
                        sBh_u + baddr);
                LDSM_X4(bl_[jp][0], bl_[jp][1], bl_[jp + 1][0], bl_[jp + 1][1],
                        sBl_u + baddr);
            }
#pragma unroll
            for (int i = 0; i < 4; i++) {
                uint32_t aaddr = (uint32_t)(((wm * 64 + i * 16 + aRowOff) * PAD2
                                            + k0 + aKOff) * 2);
                uint32_t a0, a1, a2, a3;
                LDSM_X4(a0, a1, a2, a3, sA_u + aaddr);
#pragma unroll
                for (int j = 0; j < 4; j++)
                    MMA_F16(acc[i][j], a0, a1, a2, a3, bh[j][0], bh[j][1]);
#pragma unroll
                for (int j = 0; j < 4; j++)
                    MMA_F16(acc[i][j], a0, a1, a2, a3, bl_[j][0], bl_[j][1]);
            }
        }
        __syncthreads();
    }

    const bool isL = (colBase < C1);
    __half* X = isL ? Xl : Xr;
    const float* bs = isL ? bl1 : br1;
    const int cb = isL ? colBase : colBase - C1;
#pragma unroll
    for (int i = 0; i < 4; i++) {
        int r0 = rowBase + wm * 64 + i * 16 + lr;
#pragma unroll
        for (int j = 0; j < 4; j++) {
            int c = cb + wn * 32 + j * 8 + lc;
            float b0 = bs[c], b1 = bs[c + 1];
            if (r0 < NN) {
                __half2 o = __floats2half2_rn(acc[i][j][0] + b0, acc[i][j][1] + b1);
                *(__half2*)(X + (size_t)r0 * C1 + c) = o;
            }
            if (r0 + 8 < NN) {
                __half2 o = __floats2half2_rn(acc[i][j][2] + b0, acc[i][j][3] + b1);
                *(__half2*)(X + (size_t)(r0 + 8) * C1 + c) = o;
            }
        }
    }
#undef LOAD_STAGE
}

// ============================================================================
// GEMM2 via mma.sync fp16 2-product split; outputs fp16 (+bias).
// ============================================================================
#define B2_ROWS  64
#define B2_ELEM  (B2_ROWS * PAD2)
#define B2_BYTE  (B2_ELEM * 2)        // 5120
#define STG2_BYTE (T_BYTE + 2 * B2_BYTE)       // 20480
#define SMEM2_BYTES (2 * STG2_BYTE)            // 40960

__global__ __launch_bounds__(256)
void gemm2_mma(const __half* __restrict__ Ah,
               const __half* __restrict__ Bh, const __half* __restrict__ Bl,
               const float* __restrict__ bl2, const float* __restrict__ br2,
               __half* __restrict__ Xl, __half* __restrict__ Xr)
{
    extern __shared__ __half sm[];
    const uint32_t smb = smem_u32(sm);

    const int tid  = threadIdx.x;
    const int wid  = tid >> 5;
    const int lane = tid & 31;
    const int wm   = wid & 1;
    const int wn   = wid >> 1;
    const int rowBase = blockIdx.x * 128;

    const int lr = lane >> 2;
    const int lc = (lane & 3) * 2;

    const int aRowOff = lane & 15;
    const int aKOff   = (lane >> 4) * 8;
    const int bGrp    = lane >> 3;
    const int bRowOff = (lane & 7) + (bGrp >> 1) * 8;
    const int bKOff   = (bGrp & 1) * 8;

#define LOAD_STAGE2(stg, kOff) do {                                           \
    uint32_t sb = smb + (stg) * STG2_BYTE;                                    \
    for (int idx = tid; idx < 512; idx += 256) {                              \
        int r  = idx >> 2;                                                    \
        int k8 = (idx & 3) * 8;                                               \
        uint32_t soff = (uint32_t)(r * (PAD2 * 2) + k8 * 2);                  \
        int ga = min(rowBase + r, NN - 1);                                    \
        CP16(sb + soff, Ah + (size_t)ga * C1 + (kOff) + k8);                  \
    }                                                                         \
    {                                                                         \
        int r  = tid >> 2;                                                    \
        int k8 = (tid & 3) * 8;                                               \
        uint32_t soff = (uint32_t)(r * (PAD2 * 2) + k8 * 2);                  \
        CP16(sb + T_BYTE + soff,           Bh + (size_t)r * C1 + (kOff) + k8);\
        CP16(sb + T_BYTE + B2_BYTE + soff, Bl + (size_t)r * C1 + (kOff) + k8);\
    }                                                                         \
} while (0)

    float acc[4][2][4];
#pragma unroll
    for (int i = 0; i < 4; i++)
#pragma unroll
        for (int j = 0; j < 2; j++)
#pragma unroll
            for (int f = 0; f < 4; f++) acc[i][j][f] = 0.f;

    LOAD_STAGE2(0, 0);
    CP_COMMIT();

    for (int kc = 0; kc < 8; kc++) {
        const int stg = kc & 1;
        if (kc + 1 < 8) {
            LOAD_STAGE2((kc + 1) & 1, (kc + 1) * KCH);
            CP_COMMIT();
            CP_WAIT(1);
        } else {
            CP_WAIT(0);
        }
        __syncthreads();

        const uint32_t sA_u  = smb + stg * STG2_BYTE;
        const uint32_t sBh_u = sA_u + T_BYTE;
        const uint32_t sBl_u = sBh_u + B2_BYTE;

#pragma unroll
        for (int ks = 0; ks < 2; ks++) {
            const int k0 = ks * 16;
            uint32_t bh[2][2], bl_[2][2];
            {
                uint32_t baddr = (uint32_t)(((wn * 16 + bRowOff) * PAD2
                                            + k0 + bKOff) * 2);
                LDSM_X4(bh[0][0], bh[0][1], bh[1][0], bh[1][1], sBh_u + baddr);
                LDSM_X4(bl_[0][0], bl_[0][1], bl_[1][0], bl_[1][1], sBl_u + baddr);
            }
#pragma unroll
            for (int i = 0; i < 4; i++) {
                uint32_t aaddr = (uint32_t)(((wm * 64 + i * 16 + aRowOff) * PAD2
                                            + k0 + aKOff) * 2);
                uint32_t a0, a1, a2, a3;
                LDSM_X4(a0, a1, a2, a3, sA_u + aaddr);
#pragma unroll
                for (int j = 0; j < 2; j++)
                    MMA_F16(acc[i][j], a0, a1, a2, a3, bh[j][0], bh[j][1]);
#pragma unroll
                for (int j = 0; j < 2; j++)
                    MMA_F16(acc[i][j], a0, a1, a2, a3, bl_[j][0], bl_[j][1]);
            }
        }
        __syncthreads();
    }

    const bool isL = (wn < 2);
    __half* X = isL ? Xl : Xr;
    const float* bs = isL ? bl2 : br2;
    const int cb = isL ? wn * 16 : wn * 16 - HIDC;
#pragma unroll
    for (int i = 0; i < 4; i++) {
        int r0 = rowBase + wm * 64 + i * 16 + lr;
#pragma unroll
        for (int j = 0; j < 2; j++) {
            int c = cb + j * 8 + lc;
            float b0 = bs[c], b1 = bs[c + 1];
            if (r0 < NN) {
                __half2 o = __floats2half2_rn(acc[i][j][0] + b0, acc[i][j][1] + b1);
                *(__half2*)(X + (size_t)r0 * HIDC + c) = o;
            }
            if (r0 + 8 < NN) {
                __half2 o = __floats2half2_rn(acc[i][j][2] + b0, acc[i][j][3] + b1);
                *(__half2*)(X + (size_t)(r0 + 8) * HIDC + c) = o;
            }
        }
    }
#undef LOAD_STAGE2
}

// ---------------- CSR construction ------------------------------------------
__global__ void zero_deg_k(int* __restrict__ deg)
{
    int i = blockIdx.x * blockDim.x + threadIdx.x;
    if (i < NN) deg[i] = 0;
}

__global__ void hist_k(const int* __restrict__ ei, int* __restrict__ deg)
{
    int e = blockIdx.x * blockDim.x + threadIdx.x;
    if (e < EE) atomicAdd(&deg[ei[EE + e]], 1);
}

__global__ void scan1_k(const int* __restrict__ deg, int* __restrict__ rowptr,
                        int* __restrict__ bsums)
{
    __shared__ int sh[256];
    int tid = threadIdx.x;
    int i = blockIdx.x * 256 + tid;
    int v = (i < NN) ? deg[i] : 0;
    sh[tid] = v;
    __syncthreads();
#pragma unroll
    for (int off = 1; off < 256; off <<= 1) {
        int t = (tid >= off) ? sh[tid - off] : 0;
        __syncthreads();
        sh[tid] += t;
        __syncthreads();
    }
    if (i < NN) rowptr[i] = sh[tid] - v;
    if (tid == 255) bsums[blockIdx.x] = sh[255];
}

__global__ void scan2_k(int* __restrict__ bsums, int nb)
{
    __shared__ int sh[256];
    int tid = threadIdx.x;
    int v = (tid < nb) ? bsums[tid] : 0;
    sh[tid] = v;
    __syncthreads();
#pragma unroll
    for (int off = 1; off < 256; off <<= 1) {
        int t = (tid >= off) ? sh[tid - off] : 0;
        __syncthreads();
        sh[tid] += t;
        __syncthreads();
    }
    if (tid < nb) bsums[tid] = sh[tid] - v;
}

__global__ void scan3_k(int* __restrict__ rowptr, const int* __restrict__ bsums,
                        int* __restrict__ cursor)
{
    int i = blockIdx.x * blockDim.x + threadIdx.x;
    if (i >= NN) return;
    int r = rowptr[i] + bsums[i >> 8];
    rowptr[i] = r;
    cursor[i] = r;
}

__global__ void scatter_k(const int* __restrict__ ei, int* __restrict__ cursor,
                          int* __restrict__ csrc)
{
    int e = blockIdx.x * blockDim.x + threadIdx.x;
    if (e >= EE) return;
    int d = ei[EE + e];
    int pos = atomicAdd(&cursor[d], 1);
    csrc[pos] = ei[e];
}

// ---------------- fused GATv2 edge phase, layer 1 (fp16 gathers) ------------
__global__ __launch_bounds__(256)
void edge_fused1_k(const int* __restrict__ rowptr, const int* __restrict__ deg,
                   const int* __restrict__ csrc,
                   const __half* __restrict__ xl, const __half* __restrict__ xr,
                   const float* __restrict__ att, const float* __restrict__ bias,
                   __half* __restrict__ h1)
{
    int w = (blockIdx.x * blockDim.x + threadIdx.x) >> 5;
    if (w >= NN) return;
    int lane = threadIdx.x & 31;

    float4 b0, b1;
    {
        uint4 raw = *(const uint4*)(xr + (size_t)w * C1 + lane * 8);
        float2 f0 = __half22float2(*(__half2*)&raw.x);
        float2 f1 = __half22float2(*(__half2*)&raw.y);
        float2 f2 = __half22float2(*(__half2*)&raw.z);
        float2 f3 = __half22float2(*(__half2*)&raw.w);
        b0 = make_float4(f0.x, f0.y, f1.x, f1.y);
        b1 = make_float4(f2.x, f2.y, f3.x, f3.y);
    }
    const float4* pt = reinterpret_cast<const float4*>(att + lane * 8);
    float4 t0 = pt[0], t1 = pt[1];

    float acc[8] = {};
    float den = 0.f;

    int start = rowptr[w];
    int dg    = deg[w];

    int s = (dg > 0) ? csrc[start] : 0;
    uint4 rawA = *(const uint4*)(xl + (size_t)s * C1 + lane * 8);

    for (int i = 0; i < dg; i++) {
        int snext = (i + 1 < dg) ? csrc[start + i + 1] : s;
        uint4 rawN = *(const uint4*)(xl + (size_t)snext * C1 + lane * 8);

        float2 f0 = __half22float2(*(__half2*)&rawA.x);
        float2 f1 = __half22float2(*(__half2*)&rawA.y);
        float2 f2 = __half22float2(*(__half2*)&rawA.z);
        float2 f3 = __half22float2(*(__half2*)&rawA.w);
        float4 a0 = make_float4(f0.x, f0.y, f1.x, f1.y);
        float4 a1 = make_float4(f2.x, f2.y, f3.x, f3.y);

        float p = lrelu(a0.x + b0.x) * t0.x + lrelu(a0.y + b0.y) * t0.y
                + lrelu(a0.z + b0.z) * t0.z + lrelu(a0.w + b0.w) * t0.w
                + lrelu(a1.x + b1.x) * t1.x + lrelu(a1.y + b1.y) * t1.y
                + lrelu(a1.z + b1.z) * t1.z + lrelu(a1.w + b1.w) * t1.w;
        p += __shfl_xor_sync(0xffffffffu, p, 1);
        p += __shfl_xor_sync(0xffffffffu, p, 2);
        float ex = __expf(p);
        den += ex;
        acc[0] += ex * a0.x; acc[1] += ex * a0.y;
        acc[2] += ex * a0.z; acc[3] += ex * a0.w;
        acc[4] += ex * a1.x; acc[5] += ex * a1.y;
        acc[6] += ex * a1.z; acc[7] += ex * a1.w;

        rawA = rawN;
    }

    float inv = 1.f / (den + 1e-16f);
    const float* bi = bias + lane * 8;
    __half hh[8];
#pragma unroll
    for (int j = 0; j < 8; j++)
        hh[j] = __float2half(elu(acc[j] * inv + bi[j]));
    *(uint4*)(h1 + (size_t)w * C1 + lane * 8) = *(const uint4*)hh;
}

// ---------------- fused edge phase layer 2 + head (fp16 gathers) ------------
__global__ __launch_bounds__(256)
void edge_fused2_head_k(const int* __restrict__ rowptr, const int* __restrict__ deg,
                        const int* __restrict__ csrc,
                        const __half* __restrict__ xl, const __half* __restrict__ xr,
                        const float* __restrict__ att, const float* __restrict__ bias,
                        const float* __restrict__ Wlin, const float* __restrict__ blin,
                        float* __restrict__ out)
{
    __shared__ float Ws[HIDC][OUTDIM];      // 8 KB
    __shared__ float bs[OUTDIM];

    for (int i = threadIdx.x; i < HIDC * OUTDIM; i += blockDim.x)
        Ws[i >> 6][i & 63] = Wlin[i];
    if (threadIdx.x < OUTDIM) bs[threadIdx.x] = blin[threadIdx.x];
    __syncthreads();

    int w = (blockIdx.x * blockDim.x + threadIdx.x) >> 5;
    int lane = threadIdx.x & 31;
    if (w >= NN) return;

    float b = __half2float(xr[(size_t)w * HIDC + lane]);
    float t = att[lane];

    float acc = 0.f, den = 0.f;
    int start = rowptr[w];
    int dg    = deg[w];

    int s = (dg > 0) ? csrc[start] : 0;
    float a = __half2float(xl[(size_t)s * HIDC + lane]);

    for (int i = 0; i < dg; i++) {
        int snext = (i + 1 < dg) ? csrc[start + i + 1] : s;
        float n = __half2float(xl[(size_t)snext * HIDC + lane]);

        float p = lrelu(a + b) * t;
        p += __shfl_xor_sync(0xffffffffu, p, 16);
        p += __shfl_xor_sync(0xffffffffu, p, 8);
        p += __shfl_xor_sync(0xffffffffu, p, 4);
        p += __shfl_xor_sync(0xffffffffu, p, 2);
        p += __shfl_xor_sync(0xffffffffu, p, 1);
        float ex = __expf(p);
        den += ex;
        acc += ex * a;

        a = n;
    }
    float inv = 1.f / (den + 1e-16f);
    float hval = elu(acc * inv + bias[lane]);   // h2[w][lane]

    float o0 = bs[lane];
    float o1 = bs[lane + 32];
#pragma unroll
    for (int k = 0; k < HIDC; k++) {
        float v = __shfl_sync(0xffffffffu, hval, k);
        o0 = fmaf(v, Ws[k][lane],      o0);
        o1 = fmaf(v, Ws[k][lane + 32], o1);
    }
    out[(size_t)w * OUTDIM + lane]      = o0;
    out[(size_t)w * OUTDIM + lane + 32] = o1;
}

// ---------------- launch ------------------------------------------------------
extern "C" void kernel_launch(void* const* d_in, const int* in_sizes, int n_in,
                              void* d_out, int out_size)
{
    const float* x     = (const float*)d_in[0];
    const int*   ei    = (const int*)d_in[1];
    const float* W1l   = (const float*)d_in[2];
    const float* b1l   = (const float*)d_in[3];
    const float* W1r   = (const float*)d_in[4];
    const float* b1r   = (const float*)d_in[5];
    const float* att1  = (const float*)d_in[6];
    const float* bias1 = (const float*)d_in[7];
    const float* W2l   = (const float*)d_in[8];
    const float* b2l   = (const float*)d_in[9];
    const float* W2r   = (const float*)d_in[10];
    const float* b2r   = (const float*)d_in[11];
    const float* att2  = (const float*)d_in[12];
    const float* bias2 = (const float*)d_in[13];
    const float* Wlin  = (const float*)d_in[14];
    const float* blin  = (const float*)d_in[15];
    float* out = (float*)d_out;

    int *deg, *rowptr, *cursor, *csrc, *bsums;
    __half *Ah, *Bh, *Bl, *xl1h, *xr1h, *H1, *B2h, *B2l, *xl2h, *xr2h;
    cudaGetSymbolAddress((void**)&deg,    g_deg);
    cudaGetSymbolAddress((void**)&rowptr, g_rowptr);
    cudaGetSymbolAddress((void**)&cursor, g_cursor);
    cudaGetSymbolAddress((void**)&csrc,   g_csrc);
    cudaGetSymbolAddress((void**)&bsums,  g_bsums);
    cudaGetSymbolAddress((void**)&Ah,   g_Ah);
    cudaGetSymbolAddress((void**)&Bh,   g_Bh);
    cudaGetSymbolAddress((void**)&Bl,   g_Bl);
    cudaGetSymbolAddress((void**)&xl1h, g_xl1h);
    cudaGetSymbolAddress((void**)&xr1h, g_xr1h);
    cudaGetSymbolAddress((void**)&H1,   g_H1);
    cudaGetSymbolAddress((void**)&B2h,  g_B2h);
    cudaGetSymbolAddress((void**)&B2l,  g_B2l);
    cudaGetSymbolAddress((void**)&xl2h, g_xl2h);
    cudaGetSymbolAddress((void**)&xr2h, g_xr2h);

    cudaFuncSetAttribute(gemm1_mma, cudaFuncAttributeMaxDynamicSharedMemorySize,
                         SMEM_BYTES);
    cudaFuncSetAttribute(gemm2_mma, cudaFuncAttributeMaxDynamicSharedMemorySize,
                         SMEM2_BYTES);

    const int TPB = 256;
    const int nScanBlocks = (NN + 255) / 256;       // 196

    // ---- stream fork: CSR build runs concurrently with conv + GEMM1 ----
    cudaStream_t s2;
    cudaStreamCreateWithFlags(&s2, cudaStreamNonBlocking);
    cudaEvent_t e1, e2;
    cudaEventCreateWithFlags(&e1, cudaEventDisableTiming);
    cudaEventCreateWithFlags(&e2, cudaEventDisableTiming);

    cudaEventRecord(e1, 0);
    cudaStreamWaitEvent(s2, e1, 0);

    // side stream: CSR pipeline + W2 conversion
    zero_deg_k<<<(NN + TPB - 1) / TPB, TPB, 0, s2>>>(deg);
    hist_k<<<(EE + TPB - 1) / TPB, TPB, 0, s2>>>(ei, deg);
    scan1_k<<<nScanBlocks, 256, 0, s2>>>(deg, rowptr, bsums);
    scan2_k<<<1, 256, 0, s2>>>(bsums, nScanBlocks);
    scan3_k<<<(NN + TPB - 1) / TPB, TPB, 0, s2>>>(rowptr, bsums, cursor);
    scatter_k<<<(EE + TPB - 1) / TPB, TPB, 0, s2>>>(ei, cursor, csrc);
    conv_w2_k<<<(NB2 * C1 + TPB - 1) / TPB, TPB, 0, s2>>>(W2l, W2r, B2h, B2l);
    cudaEventRecord(e2, s2);

    // main stream: merged conversion + GEMM1
    size_t convTot = (size_t)NN * INDIM + (size_t)NB * INDIM;
    conv_xw_k<<<(int)((convTot + TPB - 1) / TPB), TPB>>>(x, Ah, W1l, W1r, Bh, Bl);

    dim3 gg1(4, (NN + 127) / 128);
    gemm1_mma<<<gg1, TPB, SMEM_BYTES>>>(Ah, Bh, Bl, b1l, b1r, xl1h, xr1h);

    // join: edge phase needs both GEMM1 outputs and CSR
    cudaStreamWaitEvent(0, e2, 0);

    int eblocks = (NN * 32 + TPB - 1) / TPB;
    edge_fused1_k<<<eblocks, TPB>>>(rowptr, deg, csrc, xl1h, xr1h,
                                    att1, bias1, H1);

    gemm2_mma<<<(NN + 127) / 128, TPB, SMEM2_BYTES>>>(H1, B2h, B2l,
                                                      b2l, b2r, xl2h, xr2h);

    edge_fused2_head_k<<<eblocks, TPB>>>(rowptr, deg, csrc, xl2h, xr2h,
                                         att2, bias2, Wlin, blin, out);
}

// round 17
// speedup vs baseline: 1.0247x; 1.0247x over previous
#include <cuda_runtime.h>
#include <cuda_fp16.h>
#include <cstdint>

#define NN      50000
#define EE      800000
#define INDIM   256
#define HIDC    32
#define NHEADS  8
#define OUTDIM  64
#define C1      (NHEADS * HIDC)   // 256
#define NB      512
#define NB2     64
#define NEGSLOPE 0.2f

typedef unsigned long long u64;

// ---------------- scratch (device globals) ---------------------------------
__device__ int   g_deg   [NN];
__device__ int   g_rowptr[NN];
__device__ int   g_cursor[NN];
__device__ int   g_csrc  [EE];
__device__ int   g_bsums [256];
// fp16 operands
__device__ __align__(16) __half g_Ah  [(size_t)NN * INDIM];
__device__ __align__(16) __half g_Bh  [(size_t)NB * INDIM];
__device__ __align__(16) __half g_Bl  [(size_t)NB * INDIM];
__device__ __align__(16) __half g_xl1h[(size_t)NN * C1];
__device__ __align__(16) __half g_xr1h[(size_t)NN * C1];
__device__ __align__(16) __half g_H1  [(size_t)NN * C1];
__device__ __align__(16) __half g_B2h [(size_t)NB2 * C1];
__device__ __align__(16) __half g_B2l [(size_t)NB2 * C1];
__device__ __align__(16) __half g_xl2h[(size_t)NN * HIDC];
__device__ __align__(16) __half g_xr2h[(size_t)NN * HIDC];

// ---------------- helpers ---------------------------------------------------
__device__ __forceinline__ float lrelu(float v) { return v > 0.f ? v : NEGSLOPE * v; }
__device__ __forceinline__ float elu(float v)   { return v > 0.f ? v : expm1f(v); }

__device__ __forceinline__ uint32_t smem_u32(const void* p)
{
    uint32_t a;
    asm("{ .reg .u64 t; cvta.to.shared.u64 t, %1; cvt.u32.u64 %0, t; }"
        : "=r"(a) : "l"(p));
    return a;
}

// fp16 tensor-core mma (sm_80+ base)
#define MMA_F16(d, a0, a1, a2, a3, b0, b1)                                   \
    asm volatile(                                                            \
        "mma.sync.aligned.m16n8k16.row.col.f32.f16.f16.f32 "                 \
        "{%0,%1,%2,%3}, {%4,%5,%6,%7}, {%8,%9}, {%0,%1,%2,%3};"              \
        : "+f"((d)[0]), "+f"((d)[1]), "+f"((d)[2]), "+f"((d)[3])             \
        : "r"(a0), "r"(a1), "r"(a2), "r"(a3), "r"(b0), "r"(b1))

// ldmatrix (sm_75+ base)
#define LDSM_X4(r0, r1, r2, r3, addr)                                        \
    asm volatile("ldmatrix.sync.aligned.m8n8.x4.shared.b16 {%0,%1,%2,%3}, [%4];" \
                 : "=r"(r0), "=r"(r1), "=r"(r2), "=r"(r3) : "r"(addr))

// cp.async (sm_80+ base)
#define CP16(dst_u32, src_ptr) \
    asm volatile("cp.async.cg.shared.global [%0], [%1], 16;" \
                 :: "r"(dst_u32), "l"(src_ptr))
#define CP_COMMIT() asm volatile("cp.async.commit_group;" ::: "memory")
#define CP_WAIT(n)  asm volatile("cp.async.wait_group %0;" :: "n"(n) : "memory")

// ---------------- conversion kernels -----------------------------------------
__global__ void conv_xw_k(const float* __restrict__ x, __half* __restrict__ Ah,
                          const float* __restrict__ W1l, const float* __restrict__ W1r,
                          __half* __restrict__ Bh, __half* __restrict__ Bl)
{
    size_t i = (size_t)blockIdx.x * blockDim.x + threadIdx.x;
    const size_t NX = (size_t)NN * INDIM;
    if (i < NX) {
        Ah[i] = __float2half(x[i]);
    } else if (i < NX + (size_t)NB * INDIM) {
        size_t j = i - NX;
        int n = (int)(j >> 8);
        int k = (int)(j & 255);
        float v = (n < C1) ? W1l[(size_t)k * C1 + n] : W1r[(size_t)k * C1 + (n - C1)];
        __half h = __float2half(v);
        Bh[j] = h;
        Bl[j] = __float2half(v - __half2float(h));
    }
}

__global__ void conv_w2_k(const float* __restrict__ W2l, const float* __restrict__ W2r,
                          __half* __restrict__ B2h, __half* __restrict__ B2l)
{
    int i = blockIdx.x * blockDim.x + threadIdx.x;
    if (i >= NB2 * C1) return;
    int n = i >> 8;
    int k = i & 255;
    float v = (n < HIDC) ? W2l[(size_t)k * HIDC + n]
                         : W2r[(size_t)k * HIDC + (n - HIDC)];
    __half h = __float2half(v);
    B2h[i] = h;
    B2l[i] = __float2half(v - __half2float(h));
}

// ============================================================================
// GEMM1 via mma.sync fp16 2-product split; outputs fp16 (+bias).
// ============================================================================
#define KCH    32
#define PAD2   40
#define T_ELEM (128 * PAD2)
#define T_BYTE (T_ELEM * 2)          // 10240
#define STG_BYTE (3 * T_BYTE)        // 30720
#define SMEM_BYTES (2 * STG_BYTE)    // 61440

__global__ __launch_bounds__(256)
void gemm1_mma(const __half* __restrict__ Ah,
               const __half* __restrict__ Bh, const __half* __restrict__ Bl,
               const float* __restrict__ bl1, const float* __restrict__ br1,
               __half* __restrict__ Xl, __half* __restrict__ Xr)
{
    extern __shared__ __half sm[];
    const uint32_t smb = smem_u32(sm);

    const int tid  = threadIdx.x;
    const int wid  = tid >> 5;
    const int lane = tid & 31;
    const int wm   = wid & 1;
    const int wn   = wid >> 1;
    const int rowBase = blockIdx.y * 128;
    const int colBase = blockIdx.x * 128;

    const int lr = lane >> 2;
    const int lc = (lane & 3) * 2;

    const int aRowOff = lane & 15;
    const int aKOff   = (lane >> 4) * 8;
    const int bGrp    = lane >> 3;
    const int bRowOff = (lane & 7) + (bGrp >> 1) * 8;
    const int bKOff   = (bGrp & 1) * 8;

#define LOAD_STAGE(stg, kOff) do {                                            \
    uint32_t sb = smb + (stg) * STG_BYTE;                                     \
    for (int idx = tid; idx < 512; idx += 256) {                              \
        int r  = idx >> 2;                                                    \
        int k8 = (idx & 3) * 8;                                               \
        uint32_t soff = (uint32_t)(r * (PAD2 * 2) + k8 * 2);                  \
        int ga = min(rowBase + r, NN - 1);                                    \
        int gb = colBase + r;                                                 \
        CP16(sb + soff,              Ah + (size_t)ga * INDIM + (kOff) + k8);  \
        CP16(sb + T_BYTE + soff,     Bh + (size_t)gb * INDIM + (kOff) + k8);  \
        CP16(sb + 2 * T_BYTE + soff, Bl + (size_t)gb * INDIM + (kOff) + k8);  \
    }                                                                         \
} while (0)

    float acc[4][4][4];
#pragma unroll
    for (int i = 0; i < 4; i++)
#pragma unroll
        for (int j = 0; j < 4; j++)
#pragma unroll
            for (int f = 0; f < 4; f++) acc[i][j][f] = 0.f;

    LOAD_STAGE(0, 0);
    CP_COMMIT();

    for (int kc = 0; kc < 8; kc++) {
        const int stg = kc & 1;
        if (kc + 1 < 8) {
            LOAD_STAGE((kc + 1) & 1, (kc + 1) * KCH);
            CP_COMMIT();
            CP_WAIT(1);
        } else {
            CP_WAIT(0);
        }
        __syncthreads();

        const uint32_t sA_u  = smb + stg * STG_BYTE;
        const uint32_t sBh_u = sA_u + T_BYTE;
        const uint32_t sBl_u = sA_u + 2 * T_BYTE;

#pragma unroll
        for (int ks = 0; ks < 2; ks++) {
            const int k0 = ks * 16;
            uint32_t bh[4][2], bl_[4][2];
#pragma unroll
            for (int jp = 0; jp < 4; jp += 2) {
                uint32_t baddr = (uint32_t)(((wn * 32 + jp * 8 + bRowOff) * PAD2
                                            + k0 + bKOff) * 2);
                LDSM_X4(bh[jp][0], bh[jp][1], bh[jp + 1][0], bh[jp + 1][1],
                        sBh_u + baddr);
                LDSM_X4(bl_[jp][0], bl_[jp][1], bl_[jp + 1][0], bl_[jp + 1][1],
                        sBl_u + baddr);
            }
#pragma unroll
            for (int i = 0; i < 4; i++) {
                uint32_t aaddr = (uint32_t)(((wm * 64 + i * 16 + aRowOff) * PAD2
                                            + k0 + aKOff) * 2);
                uint32_t a0, a1, a2, a3;
                LDSM_X4(a0, a1, a2, a3, sA_u + aaddr);
#pragma unroll
                for (int j = 0; j < 4; j++)
                    MMA_F16(acc[i][j], a0, a1, a2, a3, bh[j][0], bh[j][1]);
#pragma unroll
                for (int j = 0; j < 4; j++)
                    MMA_F16(acc[i][j], a0, a1, a2, a3, bl_[j][0], bl_[j][1]);
            }
        }
        __syncthreads();
    }

    const bool isL = (colBase < C1);
    __half* X = isL ? Xl : Xr;
    const float* bs = isL ? bl1 : br1;
    const int cb = isL ? colBase : colBase - C1;
#pragma unroll
    for (int i = 0; i < 4; i++) {
        int r0 = rowBase + wm * 64 + i * 16 + lr;
#pragma unroll
        for (int j = 0; j < 4; j++) {
            int c = cb + wn * 32 + j * 8 + lc;
            float b0 = bs[c], b1 = bs[c + 1];
            if (r0 < NN) {
                __half2 o = __floats2half2_rn(acc[i][j][0] + b0, acc[i][j][1] + b1);
                *(__half2*)(X + (size_t)r0 * C1 + c) = o;
            }
            if (r0 + 8 < NN) {
                __half2 o = __floats2half2_rn(acc[i][j][2] + b0, acc[i][j][3] + b1);
                *(__half2*)(X + (size_t)(r0 + 8) * C1 + c) = o;
            }
        }
    }
#undef LOAD_STAGE
}

// ============================================================================
// GEMM2 via mma.sync fp16 2-product split; outputs fp16 (+bias).
// ============================================================================
#define B2_ROWS  64
#define B2_ELEM  (B2_ROWS * PAD2)
#define B2_BYTE  (B2_ELEM * 2)        // 5120
#define STG2_BYTE (T_BYTE + 2 * B2_BYTE)       // 20480
#define SMEM2_BYTES (2 * STG2_BYTE)            // 40960

__global__ __launch_bounds__(256)
void gemm2_mma(const __half* __restrict__ Ah,
               const __half* __restrict__ Bh, const __half* __restrict__ Bl,
               const float* __restrict__ bl2, const float* __restrict__ br2,
               __half* __restrict__ Xl, __half* __restrict__ Xr)
{
    extern __shared__ __half sm[];
    const uint32_t smb = smem_u32(sm);

    const int tid  = threadIdx.x;
    const int wid  = tid >> 5;
    const int lane = tid & 31;
    const int wm   = wid & 1;
    const int wn   = wid >> 1;
    const int rowBase = blockIdx.x * 128;

    const int lr = lane >> 2;
    const int lc = (lane & 3) * 2;

    const int aRowOff = lane & 15;
    const int aKOff   = (lane >> 4) * 8;
    const int bGrp    = lane >> 3;
    const int bRowOff = (lane & 7) + (bGrp >> 1) * 8;
    const int bKOff   = (bGrp & 1) * 8;

#define LOAD_STAGE2(stg, kOff) do {                                           \
    uint32_t sb = smb + (stg) * STG2_BYTE;                                    \
    for (int idx = tid; idx < 512; idx += 256) {                              \
        int r  = idx >> 2;                                                    \
        int k8 = (idx & 3) * 8;                                               \
        uint32_t soff = (uint32_t)(r * (PAD2 * 2) + k8 * 2);                  \
        int ga = min(rowBase + r, NN - 1);                                    \
        CP16(sb + soff, Ah + (size_t)ga * C1 + (kOff) + k8);                  \
    }                                                                         \
    {                                                                         \
        int r  = tid >> 2;                                                    \
        int k8 = (tid & 3) * 8;                                               \
        uint32_t soff = (uint32_t)(r * (PAD2 * 2) + k8 * 2);                  \
        CP16(sb + T_BYTE + soff,           Bh + (size_t)r * C1 + (kOff) + k8);\
        CP16(sb + T_BYTE + B2_BYTE + soff, Bl + (size_t)r * C1 + (kOff) + k8);\
    }                                                                         \
} while (0)

    float acc[4][2][4];
#pragma unroll
    for (int i = 0; i < 4; i++)
#pragma unroll
        for (int j = 0; j < 2; j++)
#pragma unroll
            for (int f = 0; f < 4; f++) acc[i][j][f] = 0.f;

    LOAD_STAGE2(0, 0);
    CP_COMMIT();

    for (int kc = 0; kc < 8; kc++) {
        const int stg = kc & 1;
        if (kc + 1 < 8) {
            LOAD_STAGE2((kc + 1) & 1, (kc + 1) * KCH);
            CP_COMMIT();
            CP_WAIT(1);
        } else {
            CP_WAIT(0);
        }
        __syncthreads();

        const uint32_t sA_u  = smb + stg * STG2_BYTE;
        const uint32_t sBh_u = sA_u + T_BYTE;
        const uint32_t sBl_u = sBh_u + B2_BYTE;

#pragma unroll
        for (int ks = 0; ks < 2; ks++) {
            const int k0 = ks * 16;
            uint32_t bh[2][2], bl_[2][2];
            {
                uint32_t baddr = (uint32_t)(((wn * 16 + bRowOff) * PAD2
                                            + k0 + bKOff) * 2);
                LDSM_X4(bh[0][0], bh[0][1], bh[1][0], bh[1][1], sBh_u + baddr);
                LDSM_X4(bl_[0][0], bl_[0][1], bl_[1][0], bl_[1][1], sBl_u + baddr);
            }
#pragma unroll
            for (int i = 0; i < 4; i++) {
                uint32_t aaddr = (uint32_t)(((wm * 64 + i * 16 + aRowOff) * PAD2
                                            + k0 + aKOff) * 2);
                uint32_t a0, a1, a2, a3;
                LDSM_X4(a0, a1, a2, a3, sA_u + aaddr);
#pragma unroll
                for (int j = 0; j < 2; j++)
                    MMA_F16(acc[i][j], a0, a1, a2, a3, bh[j][0], bh[j][1]);
#pragma unroll
                for (int j = 0; j < 2; j++)
                    MMA_F16(acc[i][j], a0, a1, a2, a3, bl_[j][0], bl_[j][1]);
            }
        }
        __syncthreads();
    }

    const bool isL = (wn < 2);
    __half* X = isL ? Xl : Xr;
    const float* bs = isL ? bl2 : br2;
    const int cb = isL ? wn * 16 : wn * 16 - HIDC;
#pragma unroll
    for (int i = 0; i < 4; i++) {
        int r0 = rowBase + wm * 64 + i * 16 + lr;
#pragma unroll
        for (int j = 0; j < 2; j++) {
            int c = cb + j * 8 + lc;
            float b0 = bs[c], b1 = bs[c + 1];
            if (r0 < NN) {
                __half2 o = __floats2half2_rn(acc[i][j][0] + b0, acc[i][j][1] + b1);
                *(__half2*)(X + (size_t)r0 * HIDC + c) = o;
            }
            if (r0 + 8 < NN) {
                __half2 o = __floats2half2_rn(acc[i][j][2] + b0, acc[i][j][3] + b1);
                *(__half2*)(X + (size_t)(r0 + 8) * HIDC + c) = o;
            }
        }
    }
#undef LOAD_STAGE2
}

// ---------------- CSR construction ------------------------------------------
__global__ void zero_deg_k(int* __restrict__ deg)
{
    int i = blockIdx.x * blockDim.x + threadIdx.x;
    if (i < NN) deg[i] = 0;
}

__global__ void hist_k(const int* __restrict__ ei, int* __restrict__ deg)
{
    int e = blockIdx.x * blockDim.x + threadIdx.x;
    if (e < EE) atomicAdd(&deg[ei[EE + e]], 1);
}

__global__ void scan1_k(const int* __restrict__ deg, int* __restrict__ rowptr,
                        int* __restrict__ bsums)
{
    __shared__ int sh[256];
    int tid = threadIdx.x;
    int i = blockIdx.x * 256 + tid;
    int v = (i < NN) ? deg[i] : 0;
    sh[tid] = v;
    __syncthreads();
#pragma unroll
    for (int off = 1; off < 256; off <<= 1) {
        int t = (tid >= off) ? sh[tid - off] : 0;
        __syncthreads();
        sh[tid] += t;
        __syncthreads();
    }
    if (i < NN) rowptr[i] = sh[tid] - v;
    if (tid == 255) bsums[blockIdx.x] = sh[255];
}

__global__ void scan2_k(int* __restrict__ bsums, int nb)
{
    __shared__ int sh[256];
    int tid = threadIdx.x;
    int v = (tid < nb) ? bsums[tid] : 0;
    sh[tid] = v;
    __syncthreads();
#pragma unroll
    for (int off = 1; off < 256; off <<= 1) {
        int t = (tid >= off) ? sh[tid - off] : 0;
        __syncthreads();
        sh[tid] += t;
        __syncthreads();
    }
    if (tid < nb) bsums[tid] = sh[tid] - v;
}

__global__ void scan3_k(int* __restrict__ rowptr, const int* __restrict__ bsums,
                        int* __restrict__ cursor)
{
    int i = blockIdx.x * blockDim.x + threadIdx.x;
    if (i >= NN) return;
    int r = rowptr[i] + bsums[i >> 8];
    rowptr[i] = r;
    cursor[i] = r;
}

__global__ void scatter_k(const int* __restrict__ ei, int* __restrict__ cursor,
                          int* __restrict__ csrc)
{
    int e = blockIdx.x * blockDim.x + threadIdx.x;
    if (e >= EE) return;
    int d = ei[EE + e];
    int pos = atomicAdd(&cursor[d], 1);
    csrc[pos] = ei[e];
}

// ---------------- fused GATv2 edge phase, layer 1 (fp16 gathers) ------------
__global__ __launch_bounds__(256)
void edge_fused1_k(const int* __restrict__ rowptr, const int* __restrict__ deg,
                   const int* __restrict__ csrc,
                   const __half* __restrict__ xl, const __half* __restrict__ xr,
                   const float* __restrict__ att, const float* __restrict__ bias,
                   __half* __restrict__ h1)
{
    int w = (blockIdx.x * blockDim.x + threadIdx.x) >> 5;
    if (w >= NN) return;
    int lane = threadIdx.x & 31;

    float4 b0, b1;
    {
        uint4 raw = *(const uint4*)(xr + (size_t)w * C1 + lane * 8);
        float2 f0 = __half22float2(*(__half2*)&raw.x);
        float2 f1 = __half22float2(*(__half2*)&raw.y);
        float2 f2 = __half22float2(*(__half2*)&raw.z);
        float2 f3 = __half22float2(*(__half2*)&raw.w);
        b0 = make_float4(f0.x, f0.y, f1.x, f1.y);
        b1 = make_float4(f2.x, f2.y, f3.x, f3.y);
    }
    const float4* pt = reinterpret_cast<const float4*>(att + lane * 8);
    float4 t0 = pt[0], t1 = pt[1];

    float acc[8] = {};
    float den = 0.f;

    int start = rowptr[w];
    int dg    = deg[w];

    int s = (dg > 0) ? csrc[start] : 0;
    uint4 rawA = *(const uint4*)(xl + (size_t)s * C1 + lane * 8);

    for (int i = 0; i < dg; i++) {
        int snext = (i + 1 < dg) ? csrc[start + i + 1] : s;
        uint4 rawN = *(const uint4*)(xl + (size_t)snext * C1 + lane * 8);

        float2 f0 = __half22float2(*(__half2*)&rawA.x);
        float2 f1 = __half22float2(*(__half2*)&rawA.y);
        float2 f2 = __half22float2(*(__half2*)&rawA.z);
        float2 f3 = __half22float2(*(__half2*)&rawA.w);
        float4 a0 = make_float4(f0.x, f0.y, f1.x, f1.y);
        float4 a1 = make_float4(f2.x, f2.y, f3.x, f3.y);

        float p = lrelu(a0.x + b0.x) * t0.x + lrelu(a0.y + b0.y) * t0.y
                + lrelu(a0.z + b0.z) * t0.z + lrelu(a0.w + b0.w) * t0.w
                + lrelu(a1.x + b1.x) * t1.x + lrelu(a1.y + b1.y) * t1.y
                + lrelu(a1.z + b1.z) * t1.z + lrelu(a1.w + b1.w) * t1.w;
        p += __shfl_xor_sync(0xffffffffu, p, 1);
        p += __shfl_xor_sync(0xffffffffu, p, 2);
        float ex = __expf(p);
        den += ex;
        acc[0] += ex * a0.x; acc[1] += ex * a0.y;
        acc[2] += ex * a0.z; acc[3] += ex * a0.w;
        acc[4] += ex * a1.x; acc[5] += ex * a1.y;
        acc[6] += ex * a1.z; acc[7] += ex * a1.w;

        rawA = rawN;
    }

    float inv = 1.f / (den + 1e-16f);
    const float* bi = bias + lane * 8;
    __half hh[8];
#pragma unroll
    for (int j = 0; j < 8; j++)
        hh[j] = __float2half(elu(acc[j] * inv + bi[j]));
    *(uint4*)(h1 + (size_t)w * C1 + lane * 8) = *(const uint4*)hh;
}

// ---------------- fused edge phase layer 2 + head: 4 edges per warp-pass ----
// warp = 4 groups x 8 lanes; group g handles edge i+g, lane covers 4 channels.
__global__ __launch_bounds__(256)
void edge_fused2_head_k(const int* __restrict__ rowptr, const int* __restrict__ deg,
                        const int* __restrict__ csrc,
                        const __half* __restrict__ xl, const __half* __restrict__ xr,
                        const float* __restrict__ att, const float* __restrict__ bias,
                        const float* __restrict__ Wlin, const float* __restrict__ blin,
                        float* __restrict__ out)
{
    __shared__ float Ws[HIDC][OUTDIM];      // 8 KB
    __shared__ float bs[OUTDIM];

    for (int i = threadIdx.x; i < HIDC * OUTDIM; i += blockDim.x)
        Ws[i >> 6][i & 63] = Wlin[i];
    if (threadIdx.x < OUTDIM) bs[threadIdx.x] = blin[threadIdx.x];
    __syncthreads();

    int w = (blockIdx.x * blockDim.x + threadIdx.x) >> 5;
    int lane = threadIdx.x & 31;
    if (w >= NN) return;

    const int g  = lane >> 3;          // edge group 0..3
    const int c4 = (lane & 7) * 4;     // channel base 0..28

    // xr[d] channels c4..c4+3
    float b[4];
    {
        uint2 raw = *(const uint2*)(xr + (size_t)w * HIDC + c4);
        float2 f0 = __half22float2(*(__half2*)&raw.x);
        float2 f1 = __half22float2(*(__half2*)&raw.y);
        b[0] = f0.x; b[1] = f0.y; b[2] = f1.x; b[3] = f1.y;
    }
    float4 tv = *(const float4*)(att + c4);
    float t[4] = {tv.x, tv.y, tv.z, tv.w};

    float acc[4] = {};
    float den = 0.f;

    int start = rowptr[w];
    int dg    = deg[w];

    for (int i = 0; i < dg; i += 4) {
        int e = i + g;
        int idx = min(e, dg - 1);
        int s = csrc[start + idx];
        float a[4];
        {
            uint2 raw = *(const uint2*)(xl + (size_t)s * HIDC + c4);
            float2 f0 = __half22float2(*(__half2*)&raw.x);
            float2 f1 = __half22float2(*(__half2*)&raw.y);
            a[0] = f0.x; a[1] = f0.y; a[2] = f1.x; a[3] = f1.y;
        }
        float p = lrelu(a[0] + b[0]) * t[0] + lrelu(a[1] + b[1]) * t[1]
                + lrelu(a[2] + b[2]) * t[2] + lrelu(a[3] + b[3]) * t[3];
        // reduce within the 8-lane group
        p += __shfl_xor_sync(0xffffffffu, p, 1);
        p += __shfl_xor_sync(0xffffffffu, p, 2);
        p += __shfl_xor_sync(0xffffffffu, p, 4);
        float ex = (e < dg) ? __expf(p) : 0.f;
        den += ex;
        acc[0] += ex * a[0]; acc[1] += ex * a[1];
        acc[2] += ex * a[2]; acc[3] += ex * a[3];
    }

    // cross-group reduce (groups differ in lane bits 3,4)
#pragma unroll
    for (int j = 0; j < 4; j++) {
        acc[j] += __shfl_xor_sync(0xffffffffu, acc[j], 8);
        acc[j] += __shfl_xor_sync(0xffffffffu, acc[j], 16);
    }
    den += __shfl_xor_sync(0xffffffffu, den, 8);
    den += __shfl_xor_sync(0xffffffffu, den, 16);

    float inv = 1.f / (den + 1e-16f);
    float hv[4];
#pragma unroll
    for (int j = 0; j < 4; j++)
        hv[j] = elu(acc[j] * inv + bias[c4 + j]);

    // reconstruct per-lane hval: channel = lane, held by lane (lane>>2), comp lane&3
    float h0 = __shfl_sync(0xffffffffu, hv[0], lane >> 2);
    float h1v = __shfl_sync(0xffffffffu, hv[1], lane >> 2);
    float h2v = __shfl_sync(0xffffffffu, hv[2], lane >> 2);
    float h3v = __shfl_sync(0xffffffffu, hv[3], lane >> 2);
    int sel = lane & 3;
    float hval = (sel == 0) ? h0 : (sel == 1) ? h1v : (sel == 2) ? h2v : h3v;

    float o0 = bs[lane];
    float o1 = bs[lane + 32];
#pragma unroll
    for (int k = 0; k < HIDC; k++) {
        float v = __shfl_sync(0xffffffffu, hval, k);
        o0 = fmaf(v, Ws[k][lane],      o0);
        o1 = fmaf(v, Ws[k][lane + 32], o1);
    }
    out[(size_t)w * OUTDIM + lane]      = o0;
    out[(size_t)w * OUTDIM + lane + 32] = o1;
}

// ---------------- launch ------------------------------------------------------
extern "C" void kernel_launch(void* const* d_in, const int* in_sizes, int n_in,
                              void* d_out, int out_size)
{
    const float* x     = (const float*)d_in[0];
    const int*   ei    = (const int*)d_in[1];
    const float* W1l   = (const float*)d_in[2];
    const float* b1l   = (const float*)d_in[3];
    const float* W1r   = (const float*)d_in[4];
    const float* b1r   = (const float*)d_in[5];
    const float* att1  = (const float*)d_in[6];
    const float* bias1 = (const float*)d_in[7];
    const float* W2l   = (const float*)d_in[8];
    const float* b2l   = (const float*)d_in[9];
    const float* W2r   = (const float*)d_in[10];
    const float* b2r   = (const float*)d_in[11];
    const float* att2  = (const float*)d_in[12];
    const float* bias2 = (const float*)d_in[13];
    const float* Wlin  = (const float*)d_in[14];
    const float* blin  = (const float*)d_in[15];
    float* out = (float*)d_out;

    int *deg, *rowptr, *cursor, *csrc, *bsums;
    __half *Ah, *Bh, *Bl, *xl1h, *xr1h, *H1, *B2h, *B2l, *xl2h, *xr2h;
    cudaGetSymbolAddress((void**)&deg,    g_deg);
    cudaGetSymbolAddress((void**)&rowptr, g_rowptr);
    cudaGetSymbolAddress((void**)&cursor, g_cursor);
    cudaGetSymbolAddress((void**)&csrc,   g_csrc);
    cudaGetSymbolAddress((void**)&bsums,  g_bsums);
    cudaGetSymbolAddress((void**)&Ah,   g_Ah);
    cudaGetSymbolAddress((void**)&Bh,   g_Bh);
    cudaGetSymbolAddress((void**)&Bl,   g_Bl);
    cudaGetSymbolAddress((void**)&xl1h, g_xl1h);
    cudaGetSymbolAddress((void**)&xr1h, g_xr1h);
    cudaGetSymbolAddress((void**)&H1,   g_H1);
    cudaGetSymbolAddress((void**)&B2h,  g_B2h);
    cudaGetSymbolAddress((void**)&B2l,  g_B2l);
    cudaGetSymbolAddress((void**)&xl2h, g_xl2h);
    cudaGetSymbolAddress((void**)&xr2h, g_xr2h);

    cudaFuncSetAttribute(gemm1_mma, cudaFuncAttributeMaxDynamicSharedMemorySize,
                         SMEM_BYTES);
    cudaFuncSetAttribute(gemm2_mma, cudaFuncAttributeMaxDynamicSharedMemorySize,
                         SMEM2_BYTES);

    const int TPB = 256;
    const int nScanBlocks = (NN + 255) / 256;       // 196

    // ---- stream fork: CSR build runs concurrently with conv + GEMM1 ----
    cudaStream_t s2;
    cudaStreamCreateWithFlags(&s2, cudaStreamNonBlocking);
    cudaEvent_t e1, e2;
    cudaEventCreateWithFlags(&e1, cudaEventDisableTiming);
    cudaEventCreateWithFlags(&e2, cudaEventDisableTiming);

    cudaEventRecord(e1, 0);
    cudaStreamWaitEvent(s2, e1, 0);

    // side stream: CSR pipeline + W2 conversion
    zero_deg_k<<<(NN + TPB - 1) / TPB, TPB, 0, s2>>>(deg);
    hist_k<<<(EE + TPB - 1) / TPB, TPB, 0, s2>>>(ei, deg);
    scan1_k<<<nScanBlocks, 256, 0, s2>>>(deg, rowptr, bsums);
    scan2_k<<<1, 256, 0, s2>>>(bsums, nScanBlocks);
    scan3_k<<<(NN + TPB - 1) / TPB, TPB, 0, s2>>>(rowptr, bsums, cursor);
    scatter_k<<<(EE + TPB - 1) / TPB, TPB, 0, s2>>>(ei, cursor, csrc);
    conv_w2_k<<<(NB2 * C1 + TPB - 1) / TPB, TPB, 0, s2>>>(W2l, W2r, B2h, B2l);
    cudaEventRecord(e2, s2);

    // main stream: merged conversion + GEMM1
    size_t convTot = (size_t)NN * INDIM + (size_t)NB * INDIM;
    conv_xw_k<<<(int)((convTot + TPB - 1) / TPB), TPB>>>(x, Ah, W1l, W1r, Bh, Bl);

    dim3 gg1(4, (NN + 127) / 128);
    gemm1_mma<<<gg1, TPB, SMEM_BYTES>>>(Ah, Bh, Bl, b1l, b1r, xl1h, xr1h);

    // join: edge phase needs both GEMM1 outputs and CSR
    cudaStreamWaitEvent(0, e2, 0);

    int eblocks = (NN * 32 + TPB - 1) / TPB;
    edge_fused1_k<<<eblocks, TPB>>>(rowptr, deg, csrc, xl1h, xr1h,
                                    att1, bias1, H1);

    gemm2_mma<<<(NN + 127) / 128, TPB, SMEM2_BYTES>>>(H1, B2h, B2l,
                                                      b2l, b2r, xl2h, xr2h);

    edge_fused2_head_k<<<eblocks, TPB>>>(rowptr, deg, csrc, xl2h, xr2h,
                                         att2, bias2, Wlin, blin, out);
}